// round 10
// baseline (speedup 1.0000x reference)
#include <cuda_runtime.h>
#include <cstdint>

#define NNODES 100000
#define NEDGES 800000
#define DIM    128
#define KTOT   384
#define KC     32
#define NCHUNK 12

// ---------------- scratch ----------------------------------------------------
__device__ float g_agg_in [(size_t)NNODES * DIM];
__device__ float g_agg_out[(size_t)NNODES * DIM];
__device__ int   g_cnt_in [NNODES];
__device__ int   g_cnt_out[NNODES];
__device__ int   g_start_in [NNODES];
__device__ int   g_start_out[NNODES];
__device__ int   g_fill_in [NNODES];
__device__ int   g_fill_out[NNODES];
__device__ int   g_eidx_in [NEDGES];
__device__ int   g_eidx_out[NEDGES];
__device__ int   g_total[2];
__device__ int   g_is64;
__device__ unsigned int g_wt[(size_t)KTOT * DIM];   // W_cat as tf32, [k][n]

// ---------------- PTX helpers ------------------------------------------------
__device__ __forceinline__ unsigned int f2tf32(float f) {
    unsigned int u;
    asm("cvt.rna.tf32.f32 %0, %1;" : "=r"(u) : "f"(f));
    return u;
}
__device__ __forceinline__ unsigned int raw2tf32(unsigned int r) {
    return f2tf32(__uint_as_float(r));
}
__device__ __forceinline__ uint32_t smem_u32(const void* p) {
    uint32_t a;
    asm("{ .reg .u64 t; cvta.to.shared.u64 t, %1; cvt.u32.u64 %0, t; }" : "=r"(a) : "l"(p));
    return a;
}
__device__ __forceinline__ void cp16(uint32_t dst, const void* src, int srcsize) {
    asm volatile("cp.async.cg.shared.global [%0], [%1], 16, %2;"
                 :: "r"(dst), "l"(src), "r"(srcsize) : "memory");
}
#define CP_COMMIT() asm volatile("cp.async.commit_group;" ::: "memory")
#define CP_WAIT1()  asm volatile("cp.async.wait_group 1;" ::: "memory")

__device__ __forceinline__ void mma_tf32(float* d, const unsigned* a, const unsigned* b) {
    asm volatile("mma.sync.aligned.m16n8k8.row.col.f32.tf32.tf32.f32 "
        "{%0,%1,%2,%3}, {%4,%5,%6,%7}, {%8,%9}, {%0,%1,%2,%3};"
        : "+f"(d[0]), "+f"(d[1]), "+f"(d[2]), "+f"(d[3])
        : "r"(a[0]), "r"(a[1]), "r"(a[2]), "r"(a[3]), "r"(b[0]), "r"(b[1]));
}

// ---------------- kernel 0a: edge dtype detection ---------------------------
__global__ void detect_kernel(const void* ei, int nedges, int nnodes)
{
    const long long* p = (const long long*)ei;
    int m = nedges < 64 ? nedges : 64;
    int ok = 1;
    for (int i = 0; i < m; i++) {
        long long v = p[i];
        if (v < 0 || v >= nnodes) { ok = 0; break; }
    }
    g_is64 = ok;
}

// ---------------- kernel 0b: W_cat -> tf32, [k][n] --------------------------
__global__ __launch_bounds__(256)
void wt_kernel(const float* __restrict__ Wself, const float* __restrict__ Ws2d,
               const float* __restrict__ Wd2s, unsigned int* __restrict__ wt)
{
    int idx = blockIdx.x * 256 + threadIdx.x;
    if (idx >= KTOT * DIM) return;
    int k = idx >> 7;
    int nn = idx & 127;
    const float* W = (k < DIM) ? Wself : ((k < 2 * DIM) ? Ws2d : Wd2s);
    wt[idx] = f2tf32(W[(size_t)(k & 127) * DIM + nn]);
}

// ---------------- vectorized 4-edge fetch ------------------------------------
__device__ __forceinline__ void edges4(const void* ei, int e4, int ne, int nn,
                                       int* s, int* d, bool* ok)
{
    if (g_is64) {
        const long long* p = (const long long*)ei;
        longlong2 sa = *(const longlong2*)(p + e4);
        longlong2 sb = *(const longlong2*)(p + e4 + 2);
        longlong2 da = *(const longlong2*)(p + ne + e4);
        longlong2 db = *(const longlong2*)(p + ne + e4 + 2);
        long long sv[4] = {sa.x, sa.y, sb.x, sb.y};
        long long dv[4] = {da.x, da.y, db.x, db.y};
        #pragma unroll
        for (int i = 0; i < 4; i++) {
            ok[i] = !(sv[i] < 0 || sv[i] >= nn || dv[i] < 0 || dv[i] >= nn);
            s[i] = (int)sv[i]; d[i] = (int)dv[i];
        }
    } else {
        const int* p = (const int*)ei;
        int4 sv = *(const int4*)(p + e4);
        int4 dv = *(const int4*)(p + ne + e4);
        int ss[4] = {sv.x, sv.y, sv.z, sv.w};
        int dd[4] = {dv.x, dv.y, dv.z, dv.w};
        #pragma unroll
        for (int i = 0; i < 4; i++) {
            ok[i] = !(ss[i] < 0 || ss[i] >= nn || dd[i] < 0 || dd[i] >= nn);
            s[i] = ss[i]; d[i] = dd[i];
        }
    }
}

// ---------------- kernel 1: degree count (4 edges/thread) -------------------
__global__ __launch_bounds__(256)
void count_kernel(const void* __restrict__ ei,
                  int* __restrict__ cnt_in, int* __restrict__ cnt_out,
                  int nedges, int nnodes)
{
    int e4 = (blockIdx.x * 256 + threadIdx.x) * 4;
    if (e4 >= nedges) return;
    int s[4], d[4]; bool ok[4];
    if (e4 + 4 <= nedges) {
        edges4(ei, e4, nedges, nnodes, s, d, ok);
        #pragma unroll
        for (int i = 0; i < 4; i++) if (ok[i]) {
            atomicAdd(cnt_in + d[i], 1);
            atomicAdd(cnt_out + s[i], 1);
        }
    } else {
        for (int e = e4; e < nedges; e++) {
            long long sv, dv;
            if (g_is64) { const long long* p = (const long long*)ei; sv = p[e]; dv = p[nedges + e]; }
            else        { const int* p = (const int*)ei; sv = p[e]; dv = p[nedges + e]; }
            if (sv < 0 || sv >= nnodes || dv < 0 || dv >= nnodes) continue;
            atomicAdd(cnt_in + (int)dv, 1);
            atomicAdd(cnt_out + (int)sv, 1);
        }
    }
}

// ---------------- kernel 2: segment offsets, both dirs in one launch --------
__global__ __launch_bounds__(256)
void offs_kernel(const int* __restrict__ cnt_in, const int* __restrict__ cnt_out,
                 int* __restrict__ start_in, int* __restrict__ start_out,
                 int* __restrict__ fill_in, int* __restrict__ fill_out,
                 int* __restrict__ total, int n, int nb)
{
    int dir = (blockIdx.x >= nb) ? 1 : 0;
    int blk = blockIdx.x - dir * nb;
    const int* cnt  = dir ? cnt_out  : cnt_in;
    int* start = dir ? start_out : start_in;
    int* fill  = dir ? fill_out  : fill_in;

    int i    = blk * 256 + threadIdx.x;
    int lane = threadIdx.x & 31;
    int v = (i < n) ? cnt[i] : 0;
    int p = v;
    #pragma unroll
    for (int off = 1; off < 32; off <<= 1) {
        int q = __shfl_up_sync(0xFFFFFFFFu, p, off);
        if (lane >= off) p += q;
    }
    int wtot = __shfl_sync(0xFFFFFFFFu, p, 31);
    int base = 0;
    if (lane == 31) base = atomicAdd(total + dir, wtot);
    base = __shfl_sync(0xFFFFFFFFu, base, 31);
    if (i < n) {
        int st = base + p - v;
        start[i] = st;
        fill[i]  = st;
    }
}

// ---------------- kernel 3: fill adjacency lists (4 edges/thread) -----------
__global__ __launch_bounds__(256)
void fill_kernel(const void* __restrict__ ei,
                 int* __restrict__ fill_in, int* __restrict__ fill_out,
                 int* __restrict__ eidx_in, int* __restrict__ eidx_out,
                 int nedges, int nnodes)
{
    int e4 = (blockIdx.x * 256 + threadIdx.x) * 4;
    if (e4 >= nedges) return;
    int s[4], d[4]; bool ok[4];
    if (e4 + 4 <= nedges) {
        edges4(ei, e4, nedges, nnodes, s, d, ok);
        #pragma unroll
        for (int i = 0; i < 4; i++) if (ok[i]) {
            int p0 = atomicAdd(fill_in + d[i], 1);
            eidx_in[p0] = s[i];
            int p1 = atomicAdd(fill_out + s[i], 1);
            eidx_out[p1] = d[i];
        }
    } else {
        for (int e = e4; e < nedges; e++) {
            long long sv, dv;
            if (g_is64) { const long long* p = (const long long*)ei; sv = p[e]; dv = p[nedges + e]; }
            else        { const int* p = (const int*)ei; sv = p[e]; dv = p[nedges + e]; }
            if (sv < 0 || sv >= nnodes || dv < 0 || dv >= nnodes) continue;
            int p0 = atomicAdd(fill_in + (int)dv, 1);
            eidx_in[p0] = (int)sv;
            int p1 = atomicAdd(fill_out + (int)sv, 1);
            eidx_out[p1] = (int)dv;
        }
    }
}

// ---------------- kernel 4: gather-aggregate (warp per node x dir) ----------
__global__ __launch_bounds__(256)
void gather_kernel(const float* __restrict__ x,
                   const int* __restrict__ eidx_in, const int* __restrict__ eidx_out,
                   const int* __restrict__ start_in, const int* __restrict__ start_out,
                   const int* __restrict__ cnt_in, const int* __restrict__ cnt_out,
                   float* __restrict__ agg_in, float* __restrict__ agg_out, int n)
{
    int w    = (blockIdx.x * 256 + threadIdx.x) >> 5;
    int lane = threadIdx.x & 31;
    if (w >= 2 * n) return;
    int dir  = (w >= n) ? 1 : 0;
    int node = w - dir * n;

    const int* list = dir ? eidx_out  : eidx_in;
    int deg  = dir ? cnt_out[node]   : cnt_in[node];
    int base = dir ? start_out[node] : start_in[node];

    float4 acc = make_float4(0.f, 0.f, 0.f, 0.f);
    int i = 0;
    for (; i + 4 <= deg; i += 4) {
        int i0 = __ldg(list + base + i + 0);
        int i1 = __ldg(list + base + i + 1);
        int i2 = __ldg(list + base + i + 2);
        int i3 = __ldg(list + base + i + 3);
        float4 v0 = *(const float4*)(x + (size_t)i0 * DIM + lane * 4);
        float4 v1 = *(const float4*)(x + (size_t)i1 * DIM + lane * 4);
        float4 v2 = *(const float4*)(x + (size_t)i2 * DIM + lane * 4);
        float4 v3 = *(const float4*)(x + (size_t)i3 * DIM + lane * 4);
        acc.x += (v0.x + v1.x) + (v2.x + v3.x);
        acc.y += (v0.y + v1.y) + (v2.y + v3.y);
        acc.z += (v0.z + v1.z) + (v2.z + v3.z);
        acc.w += (v0.w + v1.w) + (v2.w + v3.w);
    }
    for (; i < deg; i++) {
        int id = __ldg(list + base + i);
        float4 v = *(const float4*)(x + (size_t)id * DIM + lane * 4);
        acc.x += v.x; acc.y += v.y; acc.z += v.z; acc.w += v.w;
    }
    float s = 0.5f / (float)max(deg, 1);
    float4 o;
    o.x = acc.x * s; o.y = acc.y * s; o.z = acc.z * s; o.w = acc.w * s;
    float* dp = (dir ? agg_out : agg_in) + (size_t)node * DIM + lane * 4;
    *(float4*)dp = o;
}

// ---------------- kernel 5: tf32 GEMM, CTA 256x128, warp tile 64x64 ---------
#define MT 256
#define AP 36                      // A smem pitch (floats)
#define BP 136                     // B smem pitch (floats)
#define ABYTES (MT * AP * 4)       // 36864
#define BBYTES (KC * BP * 4)       // 17408
#define STAGE  (ABYTES + BBYTES)   // 54272
#define SMEM_TOTAL (2 * STAGE)     // 108544

__global__ __launch_bounds__(256, 1)
void gemm_kernel(const float* __restrict__ x,
                 const float* __restrict__ bself, const float* __restrict__ bs2d,
                 const float* __restrict__ bd2s,
                 const float* __restrict__ agg_in, const float* __restrict__ agg_out,
                 const unsigned int* __restrict__ wt,
                 float* __restrict__ out, int n)
{
    extern __shared__ char dsm[];
    __shared__ float sbias[DIM];
    const uint32_t sbase = smem_u32(dsm);

    const int t    = threadIdx.x;
    const int wid  = t >> 5;
    const int lane = t & 31;
    const int gid  = lane >> 2;
    const int tig  = lane & 3;
    const int row0 = blockIdx.x * MT;
    const int wm   = (wid & 3) * 64;        // 4 warps along m
    const int wn   = (wid >> 2) * 64;       // 2 warps along n

    if (t < 128) sbias[t] = bself[t] + 0.5f * (bs2d[t] + bd2s[t]);

    float acc[4][8][4];
    #pragma unroll
    for (int i = 0; i < 4; i++)
        #pragma unroll
        for (int j = 0; j < 8; j++)
            #pragma unroll
            for (int q = 0; q < 4; q++) acc[i][j][q] = 0.f;

    auto stage_copy = [&](int buf, int c) {
        const float* asrc; int koff;
        if (c < 4)      { asrc = x;       koff = c * KC; }
        else if (c < 8) { asrc = agg_in;  koff = (c - 4) * KC; }
        else            { asrc = agg_out; koff = (c - 8) * KC; }
        uint32_t abase = sbase + buf * STAGE;
        #pragma unroll
        for (int i = 0; i < 8; i++) {
            int idx = t + i * 256;             // 0..2047
            int r   = idx >> 3;                // 0..255
            int kq  = (idx & 7) * 4;           // 0..28
            int g   = row0 + r;
            int ok  = (g < n);
            int gg  = ok ? g : 0;
            cp16(abase + (uint32_t)(r * (AP * 4) + kq * 4),
                 asrc + (size_t)gg * DIM + koff + kq, ok ? 16 : 0);
        }
        uint32_t bbase = sbase + buf * STAGE + ABYTES;
        int kb = c * KC;
        #pragma unroll
        for (int i = 0; i < 4; i++) {
            int idx = t + i * 256;
            int k   = idx >> 5;
            int n4  = (idx & 31) * 4;
            cp16(bbase + (uint32_t)(k * (BP * 4) + n4 * 4),
                 wt + (size_t)(kb + k) * DIM + n4, 16);
        }
    };

    stage_copy(0, 0);
    CP_COMMIT();

    for (int c = 0; c < NCHUNK; c++) {
        if (c + 1 < NCHUNK) stage_copy((c + 1) & 1, c + 1);
        CP_COMMIT();
        CP_WAIT1();
        __syncthreads();

        const unsigned* As = (const unsigned*)(dsm + (c & 1) * STAGE);
        const unsigned* Bs = (const unsigned*)(dsm + (c & 1) * STAGE + ABYTES);

        #pragma unroll
        for (int ks = 0; ks < 4; ks++) {
            const int k0 = ks * 8;
            unsigned a[4][4];
            #pragma unroll
            for (int mt = 0; mt < 4; mt++) {
                int m = wm + mt * 16 + gid;
                a[mt][0] = raw2tf32(As[m * AP + k0 + tig]);
                a[mt][1] = raw2tf32(As[(m + 8) * AP + k0 + tig]);
                a[mt][2] = raw2tf32(As[m * AP + k0 + tig + 4]);
                a[mt][3] = raw2tf32(As[(m + 8) * AP + k0 + tig + 4]);
            }
            unsigned b[8][2];
            #pragma unroll
            for (int nt = 0; nt < 8; nt++) {
                int nn = wn + nt * 8 + gid;
                b[nt][0] = Bs[(k0 + tig) * BP + nn];
                b[nt][1] = Bs[(k0 + tig + 4) * BP + nn];
            }
            #pragma unroll
            for (int mt = 0; mt < 4; mt++)
                #pragma unroll
                for (int nt = 0; nt < 8; nt++)
                    mma_tf32(acc[mt][nt], a[mt], b[nt]);
        }
        __syncthreads();
    }

    #pragma unroll
    for (int mt = 0; mt < 4; mt++) {
        int m_lo = row0 + wm + mt * 16 + gid;
        int m_hi = m_lo + 8;
        #pragma unroll
        for (int nt = 0; nt < 8; nt++) {
            int nn = wn + nt * 8 + 2 * tig;
            float2 bv = *(float2*)&sbias[nn];
            if (m_lo < n) {
                float2 o; o.x = acc[mt][nt][0] + bv.x; o.y = acc[mt][nt][1] + bv.y;
                *(float2*)(out + (size_t)m_lo * DIM + nn) = o;
            }
            if (m_hi < n) {
                float2 o; o.x = acc[mt][nt][2] + bv.x; o.y = acc[mt][nt][3] + bv.y;
                *(float2*)(out + (size_t)m_hi * DIM + nn) = o;
            }
        }
    }
}

// ---------------- launch -----------------------------------------------------
extern "C" void kernel_launch(void* const* d_in, const int* in_sizes, int n_in,
                              void* d_out, int out_size)
{
    const float* x     = nullptr;
    const void*  ei    = nullptr;
    const float* Ws[3] = {nullptr, nullptr, nullptr};
    const float* bs[3] = {nullptr, nullptr, nullptr};
    int nw = 0, nb3 = 0;
    long long x_elems = 0, ei_elems = 0;

    for (int i = 0; i < n_in; i++) {
        long long sz = in_sizes[i];
        if (sz > 4000000)         { x = (const float*)d_in[i]; x_elems = sz; }
        else if (sz > 100000)     { ei = d_in[i]; ei_elems = sz; }
        else if (sz == DIM * DIM) { if (nw < 3) Ws[nw++] = (const float*)d_in[i]; }
        else if (sz == DIM)       { if (nb3 < 3) bs[nb3++] = (const float*)d_in[i]; }
    }
    if (!x || !ei || nw < 3 || nb3 < 3) return;

    float* out = (float*)d_out;
    int n = (int)(x_elems / DIM);
    int e = (int)(ei_elems / 2);

    void *p_ai, *p_ao, *p_ci, *p_co, *p_si, *p_so, *p_fi, *p_fo, *p_ein, *p_eout, *p_wt, *p_tot;
    cudaGetSymbolAddress(&p_ai, g_agg_in);
    cudaGetSymbolAddress(&p_ao, g_agg_out);
    cudaGetSymbolAddress(&p_ci, g_cnt_in);
    cudaGetSymbolAddress(&p_co, g_cnt_out);
    cudaGetSymbolAddress(&p_si, g_start_in);
    cudaGetSymbolAddress(&p_so, g_start_out);
    cudaGetSymbolAddress(&p_fi, g_fill_in);
    cudaGetSymbolAddress(&p_fo, g_fill_out);
    cudaGetSymbolAddress(&p_ein, g_eidx_in);
    cudaGetSymbolAddress(&p_eout, g_eidx_out);
    cudaGetSymbolAddress(&p_wt, g_wt);
    cudaGetSymbolAddress(&p_tot, g_total);

    cudaFuncSetAttribute(gemm_kernel, cudaFuncAttributeMaxDynamicSharedMemorySize, SMEM_TOTAL);

    cudaMemsetAsync(p_ci, 0, (size_t)n * sizeof(int), 0);
    cudaMemsetAsync(p_co, 0, (size_t)n * sizeof(int), 0);
    cudaMemsetAsync(p_tot, 0, 2 * sizeof(int), 0);

    detect_kernel<<<1, 1>>>(ei, e, n);
    wt_kernel<<<(KTOT * DIM + 255) / 256, 256>>>(Ws[0], Ws[1], Ws[2], (unsigned int*)p_wt);

    int e4blocks = ((e + 3) / 4 + 255) / 256;
    count_kernel<<<e4blocks, 256>>>(ei, (int*)p_ci, (int*)p_co, e, n);

    int nb = (n + 255) / 256;
    offs_kernel<<<2 * nb, 256>>>((const int*)p_ci, (const int*)p_co,
                                 (int*)p_si, (int*)p_so,
                                 (int*)p_fi, (int*)p_fo, (int*)p_tot, n, nb);

    fill_kernel<<<e4blocks, 256>>>(ei, (int*)p_fi, (int*)p_fo,
                                   (int*)p_ein, (int*)p_eout, e, n);

    int gblocks = (2 * n + 7) / 8;
    gather_kernel<<<gblocks, 256>>>(x, (const int*)p_ein, (const int*)p_eout,
                                    (const int*)p_si, (const int*)p_so,
                                    (const int*)p_ci, (const int*)p_co,
                                    (float*)p_ai, (float*)p_ao, n);

    int gemm_blocks = (n + MT - 1) / MT;
    gemm_kernel<<<gemm_blocks, 256, SMEM_TOTAL>>>(
        x, bs[0], bs[1], bs[2],
        (const float*)p_ai, (const float*)p_ao,
        (const unsigned int*)p_wt, out, n);
}

// round 14
// speedup vs baseline: 1.0836x; 1.0836x over previous
#include <cuda_runtime.h>
#include <cstdint>

#define NNODES 100000
#define NEDGES 800000
#define DIM    128
#define KTOT   384
#define KC     32
#define NCHUNK 12

// ---------------- scratch ----------------------------------------------------
__device__ float g_agg_in [(size_t)NNODES * DIM];
__device__ float g_agg_out[(size_t)NNODES * DIM];
__device__ int   g_cnt_in [NNODES];
__device__ int   g_cnt_out[NNODES];
__device__ int   g_start_in [NNODES];
__device__ int   g_start_out[NNODES];
__device__ int   g_fill_in [NNODES];
__device__ int   g_fill_out[NNODES];
__device__ int   g_eidx_in [NEDGES];
__device__ int   g_eidx_out[NEDGES];
__device__ int   g_total[2];
__device__ int   g_is64;
__device__ unsigned int g_wt[(size_t)KTOT * DIM];   // W_cat as tf32, [k][n]

// ---------------- PTX helpers ------------------------------------------------
__device__ __forceinline__ unsigned int f2tf32(float f) {
    unsigned int u;
    asm("cvt.rna.tf32.f32 %0, %1;" : "=r"(u) : "f"(f));
    return u;
}
__device__ __forceinline__ unsigned int raw2tf32(unsigned int r) {
    return f2tf32(__uint_as_float(r));
}
__device__ __forceinline__ uint32_t smem_u32(const void* p) {
    uint32_t a;
    asm("{ .reg .u64 t; cvta.to.shared.u64 t, %1; cvt.u32.u64 %0, t; }" : "=r"(a) : "l"(p));
    return a;
}
__device__ __forceinline__ void cp16(uint32_t dst, const void* src, int srcsize) {
    asm volatile("cp.async.cg.shared.global [%0], [%1], 16, %2;"
                 :: "r"(dst), "l"(src), "r"(srcsize) : "memory");
}
#define CP_COMMIT() asm volatile("cp.async.commit_group;" ::: "memory")
#define CP_WAIT1()  asm volatile("cp.async.wait_group 1;" ::: "memory")

__device__ __forceinline__ void mma_tf32(float* d, const unsigned* a, const unsigned* b) {
    asm volatile("mma.sync.aligned.m16n8k8.row.col.f32.tf32.tf32.f32 "
        "{%0,%1,%2,%3}, {%4,%5,%6,%7}, {%8,%9}, {%0,%1,%2,%3};"
        : "+f"(d[0]), "+f"(d[1]), "+f"(d[2]), "+f"(d[3])
        : "r"(a[0]), "r"(a[1]), "r"(a[2]), "r"(a[3]), "r"(b[0]), "r"(b[1]));
}

// ---------------- kernel 0a: edge dtype detection ---------------------------
__global__ void detect_kernel(const void* ei, int nedges, int nnodes)
{
    const long long* p = (const long long*)ei;
    int m = nedges < 64 ? nedges : 64;
    int ok = 1;
    for (int i = 0; i < m; i++) {
        long long v = p[i];
        if (v < 0 || v >= nnodes) { ok = 0; break; }
    }
    g_is64 = ok;
}

// ---------------- kernel 0b: W_cat -> tf32, [k][n] --------------------------
__global__ __launch_bounds__(256)
void wt_kernel(const float* __restrict__ Wself, const float* __restrict__ Ws2d,
               const float* __restrict__ Wd2s, unsigned int* __restrict__ wt)
{
    int idx = blockIdx.x * 256 + threadIdx.x;
    if (idx >= KTOT * DIM) return;
    int k = idx >> 7;
    int nn = idx & 127;
    const float* W = (k < DIM) ? Wself : ((k < 2 * DIM) ? Ws2d : Wd2s);
    wt[idx] = f2tf32(W[(size_t)(k & 127) * DIM + nn]);
}

// ---------------- vectorized 4-edge fetch ------------------------------------
__device__ __forceinline__ void edges4(const void* ei, int e4, int ne, int nn,
                                       int* s, int* d, bool* ok)
{
    if (g_is64) {
        const long long* p = (const long long*)ei;
        longlong2 sa = *(const longlong2*)(p + e4);
        longlong2 sb = *(const longlong2*)(p + e4 + 2);
        longlong2 da = *(const longlong2*)(p + ne + e4);
        longlong2 db = *(const longlong2*)(p + ne + e4 + 2);
        long long sv[4] = {sa.x, sa.y, sb.x, sb.y};
        long long dv[4] = {da.x, da.y, db.x, db.y};
        #pragma unroll
        for (int i = 0; i < 4; i++) {
            ok[i] = !(sv[i] < 0 || sv[i] >= nn || dv[i] < 0 || dv[i] >= nn);
            s[i] = (int)sv[i]; d[i] = (int)dv[i];
        }
    } else {
        const int* p = (const int*)ei;
        int4 sv = *(const int4*)(p + e4);
        int4 dv = *(const int4*)(p + ne + e4);
        int ss[4] = {sv.x, sv.y, sv.z, sv.w};
        int dd[4] = {dv.x, dv.y, dv.z, dv.w};
        #pragma unroll
        for (int i = 0; i < 4; i++) {
            ok[i] = !(ss[i] < 0 || ss[i] >= nn || dd[i] < 0 || dd[i] >= nn);
            s[i] = ss[i]; d[i] = dd[i];
        }
    }
}

// ---------------- kernel 1: degree count (4 edges/thread) -------------------
__global__ __launch_bounds__(256)
void count_kernel(const void* __restrict__ ei,
                  int* __restrict__ cnt_in, int* __restrict__ cnt_out,
                  int nedges, int nnodes)
{
    int e4 = (blockIdx.x * 256 + threadIdx.x) * 4;
    if (e4 >= nedges) return;
    int s[4], d[4]; bool ok[4];
    if (e4 + 4 <= nedges) {
        edges4(ei, e4, nedges, nnodes, s, d, ok);
        #pragma unroll
        for (int i = 0; i < 4; i++) if (ok[i]) {
            atomicAdd(cnt_in + d[i], 1);
            atomicAdd(cnt_out + s[i], 1);
        }
    } else {
        for (int e = e4; e < nedges; e++) {
            long long sv, dv;
            if (g_is64) { const long long* p = (const long long*)ei; sv = p[e]; dv = p[nedges + e]; }
            else        { const int* p = (const int*)ei; sv = p[e]; dv = p[nedges + e]; }
            if (sv < 0 || sv >= nnodes || dv < 0 || dv >= nnodes) continue;
            atomicAdd(cnt_in + (int)dv, 1);
            atomicAdd(cnt_out + (int)sv, 1);
        }
    }
}

// ---------------- kernel 2: segment offsets, both dirs in one launch --------
__global__ __launch_bounds__(256)
void offs_kernel(const int* __restrict__ cnt_in, const int* __restrict__ cnt_out,
                 int* __restrict__ start_in, int* __restrict__ start_out,
                 int* __restrict__ fill_in, int* __restrict__ fill_out,
                 int* __restrict__ total, int n, int nb)
{
    int dir = (blockIdx.x >= nb) ? 1 : 0;
    int blk = blockIdx.x - dir * nb;
    const int* cnt  = dir ? cnt_out  : cnt_in;
    int* start = dir ? start_out : start_in;
    int* fill  = dir ? fill_out  : fill_in;

    int i    = blk * 256 + threadIdx.x;
    int lane = threadIdx.x & 31;
    int v = (i < n) ? cnt[i] : 0;
    int p = v;
    #pragma unroll
    for (int off = 1; off < 32; off <<= 1) {
        int q = __shfl_up_sync(0xFFFFFFFFu, p, off);
        if (lane >= off) p += q;
    }
    int wtot = __shfl_sync(0xFFFFFFFFu, p, 31);
    int base = 0;
    if (lane == 31) base = atomicAdd(total + dir, wtot);
    base = __shfl_sync(0xFFFFFFFFu, base, 31);
    if (i < n) {
        int st = base + p - v;
        start[i] = st;
        fill[i]  = st;
    }
}

// ---------------- kernel 3: fill adjacency lists (4 edges/thread) -----------
__global__ __launch_bounds__(256)
void fill_kernel(const void* __restrict__ ei,
                 int* __restrict__ fill_in, int* __restrict__ fill_out,
                 int* __restrict__ eidx_in, int* __restrict__ eidx_out,
                 int nedges, int nnodes)
{
    int e4 = (blockIdx.x * 256 + threadIdx.x) * 4;
    if (e4 >= nedges) return;
    int s[4], d[4]; bool ok[4];
    if (e4 + 4 <= nedges) {
        edges4(ei, e4, nedges, nnodes, s, d, ok);
        #pragma unroll
        for (int i = 0; i < 4; i++) if (ok[i]) {
            int p0 = atomicAdd(fill_in + d[i], 1);
            eidx_in[p0] = s[i];
            int p1 = atomicAdd(fill_out + s[i], 1);
            eidx_out[p1] = d[i];
        }
    } else {
        for (int e = e4; e < nedges; e++) {
            long long sv, dv;
            if (g_is64) { const long long* p = (const long long*)ei; sv = p[e]; dv = p[nedges + e]; }
            else        { const int* p = (const int*)ei; sv = p[e]; dv = p[nedges + e]; }
            if (sv < 0 || sv >= nnodes || dv < 0 || dv >= nnodes) continue;
            int p0 = atomicAdd(fill_in + (int)dv, 1);
            eidx_in[p0] = (int)sv;
            int p1 = atomicAdd(fill_out + (int)sv, 1);
            eidx_out[p1] = (int)dv;
        }
    }
}

// ---------------- kernel 4: gather-aggregate (warp per node x dir) ----------
__global__ __launch_bounds__(256)
void gather_kernel(const float* __restrict__ x,
                   const int* __restrict__ eidx_in, const int* __restrict__ eidx_out,
                   const int* __restrict__ start_in, const int* __restrict__ start_out,
                   const int* __restrict__ cnt_in, const int* __restrict__ cnt_out,
                   float* __restrict__ agg_in, float* __restrict__ agg_out, int n)
{
    int w    = (blockIdx.x * 256 + threadIdx.x) >> 5;
    int lane = threadIdx.x & 31;
    if (w >= 2 * n) return;
    int dir  = (w >= n) ? 1 : 0;
    int node = w - dir * n;

    const int* list = dir ? eidx_out  : eidx_in;
    int deg  = dir ? cnt_out[node]   : cnt_in[node];
    int base = dir ? start_out[node] : start_in[node];

    float4 acc = make_float4(0.f, 0.f, 0.f, 0.f);
    int i = 0;
    for (; i + 4 <= deg; i += 4) {
        int i0 = __ldg(list + base + i + 0);
        int i1 = __ldg(list + base + i + 1);
        int i2 = __ldg(list + base + i + 2);
        int i3 = __ldg(list + base + i + 3);
        float4 v0 = *(const float4*)(x + (size_t)i0 * DIM + lane * 4);
        float4 v1 = *(const float4*)(x + (size_t)i1 * DIM + lane * 4);
        float4 v2 = *(const float4*)(x + (size_t)i2 * DIM + lane * 4);
        float4 v3 = *(const float4*)(x + (size_t)i3 * DIM + lane * 4);
        acc.x += (v0.x + v1.x) + (v2.x + v3.x);
        acc.y += (v0.y + v1.y) + (v2.y + v3.y);
        acc.z += (v0.z + v1.z) + (v2.z + v3.z);
        acc.w += (v0.w + v1.w) + (v2.w + v3.w);
    }
    for (; i < deg; i++) {
        int id = __ldg(list + base + i);
        float4 v = *(const float4*)(x + (size_t)id * DIM + lane * 4);
        acc.x += v.x; acc.y += v.y; acc.z += v.z; acc.w += v.w;
    }
    float s = 0.5f / (float)max(deg, 1);
    float4 o;
    o.x = acc.x * s; o.y = acc.y * s; o.z = acc.z * s; o.w = acc.w * s;
    float* dp = (dir ? agg_out : agg_in) + (size_t)node * DIM + lane * 4;
    *(float4*)dp = o;
}

// ---------------- kernel 5: tf32 GEMM, CTA 128x128 (R9 config, 2 CTAs/SM) ---
#define AP 36                     // A smem pitch (floats)
#define BP 136                    // B smem pitch (floats)
#define ABYTES (128 * AP * 4)     // 18432
#define BBYTES (KC * BP * 4)      // 17408
#define STAGE  (ABYTES + BBYTES)  // 35840
#define SMEM_TOTAL (2 * STAGE)    // 71680

__global__ __launch_bounds__(256, 2)
void gemm_kernel(const float* __restrict__ x,
                 const float* __restrict__ bself, const float* __restrict__ bs2d,
                 const float* __restrict__ bd2s,
                 const float* __restrict__ agg_in, const float* __restrict__ agg_out,
                 const unsigned int* __restrict__ wt,
                 float* __restrict__ out, int n)
{
    extern __shared__ char dsm[];
    __shared__ float sbias[DIM];
    const uint32_t sbase = smem_u32(dsm);

    const int t    = threadIdx.x;
    const int wid  = t >> 5;
    const int lane = t & 31;
    const int gid  = lane >> 2;
    const int tig  = lane & 3;
    const int row0 = blockIdx.x * 128;
    const int wm   = (wid & 3) * 32;
    const int wn   = (wid >> 2) * 64;

    if (t < 128) sbias[t] = bself[t] + 0.5f * (bs2d[t] + bd2s[t]);

    float acc[2][8][4];
    #pragma unroll
    for (int i = 0; i < 2; i++)
        #pragma unroll
        for (int j = 0; j < 8; j++)
            #pragma unroll
            for (int q = 0; q < 4; q++) acc[i][j][q] = 0.f;

    auto stage_copy = [&](int buf, int c) {
        const float* asrc; int koff;
        if (c < 4)      { asrc = x;       koff = c * KC; }
        else if (c < 8) { asrc = agg_in;  koff = (c - 4) * KC; }
        else            { asrc = agg_out; koff = (c - 8) * KC; }
        uint32_t abase = sbase + buf * STAGE;
        #pragma unroll
        for (int i = 0; i < 4; i++) {
            int idx = t + i * 256;
            int r   = idx >> 3;
            int kq  = (idx & 7) * 4;
            int g   = row0 + r;
            int ok  = (g < n);
            int gg  = ok ? g : 0;
            cp16(abase + (uint32_t)(r * (AP * 4) + kq * 4),
                 asrc + (size_t)gg * DIM + koff + kq, ok ? 16 : 0);
        }
        uint32_t bbase = sbase + buf * STAGE + ABYTES;
        int kb = c * KC;
        #pragma unroll
        for (int i = 0; i < 4; i++) {
            int idx = t + i * 256;
            int k   = idx >> 5;
            int n4  = (idx & 31) * 4;
            cp16(bbase + (uint32_t)(k * (BP * 4) + n4 * 4),
                 wt + (size_t)(kb + k) * DIM + n4, 16);
        }
    };

    stage_copy(0, 0);
    CP_COMMIT();

    for (int c = 0; c < NCHUNK; c++) {
        if (c + 1 < NCHUNK) stage_copy((c + 1) & 1, c + 1);
        CP_COMMIT();
        CP_WAIT1();
        __syncthreads();

        const unsigned* As = (const unsigned*)(dsm + (c & 1) * STAGE);
        const unsigned* Bs = (const unsigned*)(dsm + (c & 1) * STAGE + ABYTES);

        #pragma unroll
        for (int ks = 0; ks < 4; ks++) {
            const int k0 = ks * 8;
            unsigned a[2][4];
            #pragma unroll
            for (int mt = 0; mt < 2; mt++) {
                int m = wm + mt * 16 + gid;
                a[mt][0] = raw2tf32(As[m * AP + k0 + tig]);
                a[mt][1] = raw2tf32(As[(m + 8) * AP + k0 + tig]);
                a[mt][2] = raw2tf32(As[m * AP + k0 + tig + 4]);
                a[mt][3] = raw2tf32(As[(m + 8) * AP + k0 + tig + 4]);
            }
            unsigned b[8][2];
            #pragma unroll
            for (int nt = 0; nt < 8; nt++) {
                int nn = wn + nt * 8 + gid;
                b[nt][0] = Bs[(k0 + tig) * BP + nn];
                b[nt][1] = Bs[(k0 + tig + 4) * BP + nn];
            }
            #pragma unroll
            for (int mt = 0; mt < 2; mt++)
                #pragma unroll
                for (int nt = 0; nt < 8; nt++)
                    mma_tf32(acc[mt][nt], a[mt], b[nt]);
        }
        __syncthreads();
    }

    #pragma unroll
    for (int mt = 0; mt < 2; mt++) {
        int m_lo = row0 + wm + mt * 16 + gid;
        int m_hi = m_lo + 8;
        #pragma unroll
        for (int nt = 0; nt < 8; nt++) {
            int nn = wn + nt * 8 + 2 * tig;
            float2 bv = *(float2*)&sbias[nn];
            if (m_lo < n) {
                float2 o; o.x = acc[mt][nt][0] + bv.x; o.y = acc[mt][nt][1] + bv.y;
                *(float2*)(out + (size_t)m_lo * DIM + nn) = o;
            }
            if (m_hi < n) {
                float2 o; o.x = acc[mt][nt][2] + bv.x; o.y = acc[mt][nt][3] + bv.y;
                *(float2*)(out + (size_t)m_hi * DIM + nn) = o;
            }
        }
    }
}

// ---------------- launch -----------------------------------------------------
extern "C" void kernel_launch(void* const* d_in, const int* in_sizes, int n_in,
                              void* d_out, int out_size)
{
    const float* x     = nullptr;
    const void*  ei    = nullptr;
    const float* Ws[3] = {nullptr, nullptr, nullptr};
    const float* bs[3] = {nullptr, nullptr, nullptr};
    int nw = 0, nb3 = 0;
    long long x_elems = 0, ei_elems = 0;

    for (int i = 0; i < n_in; i++) {
        long long sz = in_sizes[i];
        if (sz > 4000000)         { x = (const float*)d_in[i]; x_elems = sz; }
        else if (sz > 100000)     { ei = d_in[i]; ei_elems = sz; }
        else if (sz == DIM * DIM) { if (nw < 3) Ws[nw++] = (const float*)d_in[i]; }
        else if (sz == DIM)       { if (nb3 < 3) bs[nb3++] = (const float*)d_in[i]; }
    }
    if (!x || !ei || nw < 3 || nb3 < 3) return;

    float* out = (float*)d_out;
    int n = (int)(x_elems / DIM);
    int e = (int)(ei_elems / 2);

    void *p_ai, *p_ao, *p_ci, *p_co, *p_si, *p_so, *p_fi, *p_fo, *p_ein, *p_eout, *p_wt, *p_tot;
    cudaGetSymbolAddress(&p_ai, g_agg_in);
    cudaGetSymbolAddress(&p_ao, g_agg_out);
    cudaGetSymbolAddress(&p_ci, g_cnt_in);
    cudaGetSymbolAddress(&p_co, g_cnt_out);
    cudaGetSymbolAddress(&p_si, g_start_in);
    cudaGetSymbolAddress(&p_so, g_start_out);
    cudaGetSymbolAddress(&p_fi, g_fill_in);
    cudaGetSymbolAddress(&p_fo, g_fill_out);
    cudaGetSymbolAddress(&p_ein, g_eidx_in);
    cudaGetSymbolAddress(&p_eout, g_eidx_out);
    cudaGetSymbolAddress(&p_wt, g_wt);
    cudaGetSymbolAddress(&p_tot, g_total);

    cudaFuncSetAttribute(gemm_kernel, cudaFuncAttributeMaxDynamicSharedMemorySize, SMEM_TOTAL);

    cudaMemsetAsync(p_ci, 0, (size_t)n * sizeof(int), 0);
    cudaMemsetAsync(p_co, 0, (size_t)n * sizeof(int), 0);
    cudaMemsetAsync(p_tot, 0, 2 * sizeof(int), 0);

    detect_kernel<<<1, 1>>>(ei, e, n);
    wt_kernel<<<(KTOT * DIM + 255) / 256, 256>>>(Ws[0], Ws[1], Ws[2], (unsigned int*)p_wt);

    int e4blocks = ((e + 3) / 4 + 255) / 256;
    count_kernel<<<e4blocks, 256>>>(ei, (int*)p_ci, (int*)p_co, e, n);

    int nb = (n + 255) / 256;
    offs_kernel<<<2 * nb, 256>>>((const int*)p_ci, (const int*)p_co,
                                 (int*)p_si, (int*)p_so,
                                 (int*)p_fi, (int*)p_fo, (int*)p_tot, n, nb);

    fill_kernel<<<e4blocks, 256>>>(ei, (int*)p_fi, (int*)p_fo,
                                   (int*)p_ein, (int*)p_eout, e, n);

    int gblocks = (2 * n + 7) / 8;
    gather_kernel<<<gblocks, 256>>>(x, (const int*)p_ein, (const int*)p_eout,
                                    (const int*)p_si, (const int*)p_so,
                                    (const int*)p_ci, (const int*)p_co,
                                    (float*)p_ai, (float*)p_ao, n);

    int gemm_blocks = (n + 127) / 128;
    gemm_kernel<<<gemm_blocks, 256, SMEM_TOTAL>>>(
        x, bs[0], bs[1], bs[2],
        (const float*)p_ai, (const float*)p_ao,
        (const unsigned int*)p_wt, out, n);
}